// round 11
// baseline (speedup 1.0000x reference)
#include <cuda_runtime.h>
#include <math.h>

#define BB   512
#define MM   32
#define NAG  8
#define HH   256
#define KH   128
#define NACT 16
#define HO   (HH * NAG)   // 2048

#define ACT_OFF  0
#define BASE_OFF 8192
#define HID_OFF  8704
#define COMM_OFF 139776

__device__ float g_csum[BB * HH];
__device__ float g_part[4 * BB * HH];    // hid partials: (mat*2 + kh)
__device__ int   g_cnt[MM];
__device__ int   g_list[MM * BB];

__global__ void k_zero() {
    if (threadIdx.x < MM) g_cnt[threadIdx.x] = 0;
}

// Per-example agent-sum + model-id grouping lists
__global__ void k_prep(const float* __restrict__ comm_in,
                       const int* __restrict__ mid) {
    int b = blockIdx.x;
    int h = threadIdx.x;
    const float* p = comm_in + b * NAG * HH + h;
    float s = 0.f;
#pragma unroll
    for (int a = 0; a < NAG; a++) s += p[a * HH];
    g_csum[b * HH + h] = s;
    if (h == 0) {
        int m = mid[b];
        int slot = atomicAdd(&g_cnt[m], 1);
        g_list[m * BB + slot] = b;
    }
}

// hid partial GEMMs. grid (32, mat*2+coltile, kh). 128 thr, 1 col/thread,
// 16-row chunks, float2 smem reads. Weight slab 64KB -> L1-resident repeats.
__global__ void __launch_bounds__(128) k_hidmm(
                      const float* __restrict__ prev_hid,
                      const float* __restrict__ Wc,
                      const float* __restrict__ Wr) {
    int m = blockIdx.x;
    int n = g_cnt[m];
    if (n == 0) return;
    int mat = blockIdx.y >> 1;
    int col = (blockIdx.y & 1) * 128 + threadIdx.x;
    int kh  = blockIdx.z;

    const float* W = (mat ? Wr : Wc) + m * HH * HH + kh * KH * HH + col;
    const float* X = (mat ? prev_hid : g_csum) + kh * KH;
    float* P = g_part + (mat * 2 + kh) * (BB * HH);

    __shared__ float hs[16][KH];      // 8KB
    __shared__ int   rows[16];

    for (int base = 0; base < n; base += 16) {
        int R = n - base; if (R > 16) R = 16;
        // stage 16 rows x 128 k as float4
        for (int f = threadIdx.x; f < 16 * (KH / 4); f += 128) {
            int r  = f >> 5;           // KH/4 = 32 float4 per row
            int k4 = f & 31;
            int rr  = (r < R) ? r : 0;
            int row = g_list[m * BB + base + rr];
            *(float4*)&hs[r][k4 * 4] = *(const float4*)&X[row * HH + k4 * 4];
            if (k4 == 0) rows[r] = row;
        }
        __syncthreads();

        float acc[16];
#pragma unroll
        for (int r = 0; r < 16; r++) acc[r] = 0.f;

        for (int k = 0; k < KH; k += 8) {
            float w[8];
#pragma unroll
            for (int u = 0; u < 8; u++) w[u] = W[(k + u) * HH];
#pragma unroll
            for (int r = 0; r < 16; r++) {
#pragma unroll
                for (int u = 0; u < 8; u += 2) {
                    float2 x2 = *(const float2*)&hs[r][k + u];
                    acc[r] = fmaf(x2.x, w[u],     acc[r]);
                    acc[r] = fmaf(x2.y, w[u + 1], acc[r]);
                }
            }
        }

        for (int r = 0; r < R; r++) P[rows[r] * HH + col] = acc[r];
        __syncthreads();
    }
}

// Fused: hid = tanh(sum of 4 partials + biases + lut); action softmax + baseline.
__global__ void __launch_bounds__(128) k_hidact(
                      const int* __restrict__ mid,
                      const float* __restrict__ bc, const float* __restrict__ br,
                      const float* __restrict__ lut, const int* __restrict__ inp,
                      const float* __restrict__ enc_bias,
                      const float* __restrict__ Wa, const float* __restrict__ ba,
                      const float* __restrict__ Wb, const float* __restrict__ bb,
                      float* __restrict__ hid,
                      float* __restrict__ act, float* __restrict__ base_out) {
    int b = blockIdx.x;
    int t = threadIdx.x;
    int m = mid[b];

    __shared__ float hsh[HH];
    __shared__ float sps[32 * 16];
    __shared__ float sb[4];

#pragma unroll
    for (int c = t; c < HH; c += 128) {
        float v = g_part[0 * BB * HH + b * HH + c]
                + g_part[1 * BB * HH + b * HH + c]
                + g_part[2 * BB * HH + b * HH + c]
                + g_part[3 * BB * HH + b * HH + c]
                + bc[m * HH + c] + br[m * HH + c]
                + enc_bias[c] + lut[inp[b] * HH + c];
        float h = tanhf(v);
        hid[b * HH + c] = h;
        hsh[c] = h;
    }
    __syncthreads();

    // action partials: aq = t&3 (4 actions each), kc = t>>2 (8 k's each)
    {
        int aq = t & 3;
        int kc = t >> 2;
        const float4* WaP = (const float4*)(Wa + m * HH * NACT + aq * 4);
        float4 a4 = make_float4(0.f, 0.f, 0.f, 0.f);
#pragma unroll
        for (int j = 0; j < 8; j++) {
            int k = kc * 8 + j;
            float4 w = WaP[k * 4];
            float x = hsh[k];
            a4.x += x * w.x; a4.y += x * w.y; a4.z += x * w.z; a4.w += x * w.w;
        }
        *(float4*)&sps[kc * 16 + aq * 4] = a4;
    }
    // baseline partial
    {
        const float* WbP = Wb + m * HH;
        float pv = hsh[t] * WbP[t] + hsh[t + 128] * WbP[t + 128];
#pragma unroll
        for (int o = 16; o > 0; o >>= 1) pv += __shfl_xor_sync(0xffffffffu, pv, o);
        if ((t & 31) == 0) sb[t >> 5] = pv;
    }
    __syncthreads();

    if (t < NACT) {
        float v = ba[m * NACT + t];
#pragma unroll
        for (int kc = 0; kc < 32; kc++) v += sps[kc * 16 + t];
        float mx = v;
#pragma unroll
        for (int o = 8; o > 0; o >>= 1) mx = fmaxf(mx, __shfl_xor_sync(0xffffu, mx, o, 16));
        float ev = expf(v - mx);
        float sum = ev;
#pragma unroll
        for (int o = 8; o > 0; o >>= 1) sum += __shfl_xor_sync(0xffffu, sum, o, 16);
        act[b * NACT + t] = ev / sum;
    }
    if (t == 0) base_out[b] = sb[0] + sb[1] + sb[2] + sb[3] + bb[m];
}

// comm_out GEMM, full K per block, direct store (no partials, no epilogue).
// grid (32, 16 col-tiles of 128). 128 thr, 1 col/thread, 16-row chunks.
// Weight slab = 128 cols x 256 K x 4B = 128KB -> crosses L2 once, L1 repeats.
__global__ void __launch_bounds__(128) k_commout(
                          const float* __restrict__ hid,
                          const float* __restrict__ Wo,
                          const float* __restrict__ bo,
                          float* __restrict__ comm) {
    int m = blockIdx.x;
    int n = g_cnt[m];
    if (n == 0) return;
    int col = blockIdx.y * 128 + threadIdx.x;

    __shared__ float hs[16][HH];      // 16KB
    __shared__ int   rows[16];

    const float* Wp = Wo + (size_t)m * HH * HO + col;
    float bov = bo[m * HO + col];

    for (int base = 0; base < n; base += 16) {
        int R = n - base; if (R > 16) R = 16;
        // stage 16 rows x 256 k as float4 (16*64 float4, 8 per thread)
        for (int f = threadIdx.x; f < 16 * (HH / 4); f += 128) {
            int r  = f >> 6;           // HH/4 = 64 float4 per row
            int k4 = f & 63;
            int rr  = (r < R) ? r : 0;
            int row = g_list[m * BB + base + rr];
            *(float4*)&hs[r][k4 * 4] = *(const float4*)&hid[row * HH + k4 * 4];
            if (k4 == 0) rows[r] = row;
        }
        __syncthreads();

        float acc[16];
#pragma unroll
        for (int r = 0; r < 16; r++) acc[r] = 0.f;

        for (int k = 0; k < HH; k += 8) {
            float w[8];
#pragma unroll
            for (int u = 0; u < 8; u++) w[u] = Wp[(size_t)(k + u) * HO];
#pragma unroll
            for (int r = 0; r < 16; r++) {
#pragma unroll
                for (int u = 0; u < 8; u += 2) {
                    float2 x2 = *(const float2*)&hs[r][k + u];
                    acc[r] = fmaf(x2.x, w[u],     acc[r]);
                    acc[r] = fmaf(x2.y, w[u + 1], acc[r]);
                }
            }
        }

        for (int r = 0; r < R; r++) {
            comm[(size_t)rows[r] * HO + col] = (acc[r] + bov) * (1.0f / 7.0f);
        }
        __syncthreads();
    }
}

extern "C" void kernel_launch(void* const* d_in, const int* in_sizes, int n_in,
                              void* d_out, int out_size) {
    const float* comm_in  = (const float*)d_in[0];
    const int*   inp      = (const int*)d_in[1];
    const float* prev_hid = (const float*)d_in[2];
    const int*   mid      = (const int*)d_in[4];
    const float* Wc       = (const float*)d_in[5];
    const float* bc       = (const float*)d_in[6];
    const float* Wr       = (const float*)d_in[7];
    const float* br       = (const float*)d_in[8];
    const float* Wa       = (const float*)d_in[9];
    const float* ba       = (const float*)d_in[10];
    const float* Wb       = (const float*)d_in[11];
    const float* bb       = (const float*)d_in[12];
    const float* Wo       = (const float*)d_in[13];
    const float* bo       = (const float*)d_in[14];
    const float* lut      = (const float*)d_in[15];
    const float* enc_bias = (const float*)d_in[16];

    float* out  = (float*)d_out;
    float* act  = out + ACT_OFF;
    float* base = out + BASE_OFF;
    float* hid  = out + HID_OFF;
    float* comm = out + COMM_OFF;

    k_zero<<<1, 32>>>();
    k_prep<<<BB, HH>>>(comm_in, mid);
    k_hidmm<<<dim3(MM, 4, 2), 128>>>(prev_hid, Wc, Wr);
    k_hidact<<<BB, 128>>>(mid, bc, br, lut, inp, enc_bias,
                          Wa, ba, Wb, bb, hid, act, base);
    k_commout<<<dim3(MM, 16), 128>>>(hid, Wo, bo, comm);
}

// round 13
// speedup vs baseline: 1.2485x; 1.2485x over previous
#include <cuda_runtime.h>
#include <math.h>

#define BB   512
#define MM   32
#define NAG  8
#define HH   256
#define KQ   64           // K quarter
#define NACT 16
#define HO   (HH * NAG)   // 2048

#define ACT_OFF  0
#define BASE_OFF 8192
#define HID_OFF  8704
#define COMM_OFF 139776

__device__ float g_csum[BB * HH];
__device__ float g_part[8 * BB * HH];    // hid partials: (mat*4 + kq)
__device__ float g_cpart[4 * BB * HO];   // comm partials per kq
__device__ int   g_cnt[MM];
__device__ int   g_list[MM * BB];

__global__ void k_zero() {
    if (threadIdx.x < MM) g_cnt[threadIdx.x] = 0;
}

// Per-example agent-sum + model-id grouping lists
__global__ void k_prep(const float* __restrict__ comm_in,
                       const int* __restrict__ mid) {
    int b = blockIdx.x;
    int h = threadIdx.x;
    const float* p = comm_in + b * NAG * HH + h;
    float s = 0.f;
#pragma unroll
    for (int a = 0; a < NAG; a++) s += p[a * HH];
    g_csum[b * HH + h] = s;
    if (h == 0) {
        int m = mid[b];
        int slot = atomicAdd(&g_cnt[m], 1);
        g_list[m * BB + slot] = b;
    }
}

// hid partial GEMMs. grid (32, mat*2+coltile, 4 kq). 128 thr, 1 col/thread,
// 16-row chunks, float2 smem reads, 32KB weight slab (L1-resident repeats).
__global__ void __launch_bounds__(128) k_hidmm(
                      const float* __restrict__ prev_hid,
                      const float* __restrict__ Wc,
                      const float* __restrict__ Wr) {
    int m = blockIdx.x;
    int n = g_cnt[m];
    if (n == 0) return;
    int mat = blockIdx.y >> 1;
    int col = (blockIdx.y & 1) * 128 + threadIdx.x;
    int kq  = blockIdx.z;

    const float* W = (mat ? Wr : Wc) + m * HH * HH + kq * KQ * HH + col;
    const float* X = (mat ? prev_hid : g_csum) + kq * KQ;
    float* P = g_part + (mat * 4 + kq) * (BB * HH);

    __shared__ float xs[16][KQ];      // 4KB
    __shared__ int   rows[16];

    for (int base = 0; base < n; base += 16) {
        int R = n - base; if (R > 16) R = 16;
        // stage 16 rows x 64 k: 16 float4 per row, 2 per thread
        for (int f = threadIdx.x; f < 16 * (KQ / 4); f += 128) {
            int r  = f >> 4;
            int k4 = f & 15;
            int rr  = (r < R) ? r : 0;
            int row = g_list[m * BB + base + rr];
            *(float4*)&xs[r][k4 * 4] = *(const float4*)&X[row * HH + k4 * 4];
            if (k4 == 0) rows[r] = row;
        }
        __syncthreads();

        float acc[16];
#pragma unroll
        for (int r = 0; r < 16; r++) acc[r] = 0.f;

        for (int k = 0; k < KQ; k += 8) {
            float w[8];
#pragma unroll
            for (int u = 0; u < 8; u++) w[u] = W[(k + u) * HH];
#pragma unroll
            for (int r = 0; r < 16; r++) {
#pragma unroll
                for (int u = 0; u < 8; u += 2) {
                    float2 x2 = *(const float2*)&xs[r][k + u];
                    acc[r] = fmaf(x2.x, w[u],     acc[r]);
                    acc[r] = fmaf(x2.y, w[u + 1], acc[r]);
                }
            }
        }

        for (int r = 0; r < R; r++) P[rows[r] * HH + col] = acc[r];
        __syncthreads();
    }
}

// Fused: hid = tanh(sum of 8 partials + biases + lut); action softmax + baseline.
// 256 threads: 1 column per thread for the partial-combine.
__global__ void __launch_bounds__(256) k_hidact(
                      const int* __restrict__ mid,
                      const float* __restrict__ bc, const float* __restrict__ br,
                      const float* __restrict__ lut, const int* __restrict__ inp,
                      const float* __restrict__ enc_bias,
                      const float* __restrict__ Wa, const float* __restrict__ ba,
                      const float* __restrict__ Wb, const float* __restrict__ bb,
                      float* __restrict__ hid,
                      float* __restrict__ act, float* __restrict__ base_out) {
    int b = blockIdx.x;
    int t = threadIdx.x;
    int m = mid[b];

    __shared__ float hsh[HH];
    __shared__ float sps[32 * 16];
    __shared__ float sb[8];

    {
        int c = t;   // 256 threads, 256 cols
        float v = bc[m * HH + c] + br[m * HH + c]
                + enc_bias[c] + lut[inp[b] * HH + c];
#pragma unroll
        for (int s = 0; s < 8; s++) v += g_part[s * (BB * HH) + b * HH + c];
        float h = tanhf(v);
        hid[b * HH + c] = h;
        hsh[c] = h;
    }
    __syncthreads();

    if (t < 128) {
        // action partials: aq = t&3 (4 actions each), kc = t>>2 (8 k's each)
        int aq = t & 3;
        int kc = t >> 2;
        const float4* WaP = (const float4*)(Wa + m * HH * NACT + aq * 4);
        float4 a4 = make_float4(0.f, 0.f, 0.f, 0.f);
#pragma unroll
        for (int j = 0; j < 8; j++) {
            int k = kc * 8 + j;
            float4 w = WaP[k * 4];
            float x = hsh[k];
            a4.x += x * w.x; a4.y += x * w.y; a4.z += x * w.z; a4.w += x * w.w;
        }
        *(float4*)&sps[kc * 16 + aq * 4] = a4;
    }
    {
        const float* WbP = Wb + m * HH;
        float pv = hsh[t] * WbP[t];
#pragma unroll
        for (int o = 16; o > 0; o >>= 1) pv += __shfl_xor_sync(0xffffffffu, pv, o);
        if ((t & 31) == 0) sb[t >> 5] = pv;
    }
    __syncthreads();

    if (t < NACT) {
        float v = ba[m * NACT + t];
#pragma unroll
        for (int kc = 0; kc < 32; kc++) v += sps[kc * 16 + t];
        float mx = v;
#pragma unroll
        for (int o = 8; o > 0; o >>= 1) mx = fmaxf(mx, __shfl_xor_sync(0xffffu, mx, o, 16));
        float ev = expf(v - mx);
        float sum = ev;
#pragma unroll
        for (int o = 8; o > 0; o >>= 1) sum += __shfl_xor_sync(0xffffu, sum, o, 16);
        act[b * NACT + t] = ev / sum;
    }
    if (t == 0) {
        float s = 0.f;
#pragma unroll
        for (int i = 0; i < 8; i++) s += sb[i];
        base_out[b] = s + bb[m];
    }
}

// comm partial GEMM. grid (32, 4 col-tiles of 512, 4 kq). 256 thr, float2/thread,
// 16-row chunks, float2 smem reads. Slab 128KB (L1-fit), 4096 warps.
__global__ void __launch_bounds__(256) k_commout(
                          const float* __restrict__ hid,
                          const float* __restrict__ Wo) {
    int m = blockIdx.x;
    int n = g_cnt[m];
    if (n == 0) return;
    int col0 = blockIdx.y * 512 + threadIdx.x * 2;
    int kq   = blockIdx.z;

    __shared__ float hs[16][KQ];      // 4KB
    __shared__ int   rows[16];

    const float2* WoP = (const float2*)(Wo + (size_t)m * HH * HO + (size_t)kq * KQ * HO + col0);
    float* P = g_cpart + (size_t)kq * BB * HO;

    for (int base = 0; base < n; base += 16) {
        int R = n - base; if (R > 16) R = 16;
        // stage 16 rows x 64 k of this kq slice: 16 float4/row, 1 per thread
        for (int f = threadIdx.x; f < 16 * (KQ / 4); f += 256) {
            int r  = f >> 4;
            int k4 = f & 15;
            int rr  = (r < R) ? r : 0;
            int row = g_list[m * BB + base + rr];
            *(float4*)&hs[r][k4 * 4] = *(const float4*)&hid[row * HH + kq * KQ + k4 * 4];
            if (k4 == 0) rows[r] = row;
        }
        __syncthreads();

        float2 acc[16];
#pragma unroll
        for (int r = 0; r < 16; r++) { acc[r].x = 0.f; acc[r].y = 0.f; }

        for (int k = 0; k < KQ; k += 8) {
            float2 w[8];
#pragma unroll
            for (int u = 0; u < 8; u++) w[u] = WoP[(k + u) * (HO / 2)];
#pragma unroll
            for (int r = 0; r < 16; r++) {
#pragma unroll
                for (int u = 0; u < 8; u += 2) {
                    float2 x2 = *(const float2*)&hs[r][k + u];
                    acc[r].x = fmaf(x2.x, w[u].x,     acc[r].x);
                    acc[r].y = fmaf(x2.x, w[u].y,     acc[r].y);
                    acc[r].x = fmaf(x2.y, w[u + 1].x, acc[r].x);
                    acc[r].y = fmaf(x2.y, w[u + 1].y, acc[r].y);
                }
            }
        }

        for (int r = 0; r < R; r++) {
            int row = rows[r];
            *(float2*)(P + (size_t)row * HO + col0) = acc[r];
        }
        __syncthreads();
    }
}

// comm epilogue: comm = (p0+p1+p2+p3 + bo[m]) / 7. grid (1024, 256), float4/thread.
__global__ void __launch_bounds__(256) k_commep(
                        const int* __restrict__ mid,
                        const float* __restrict__ bo,
                        float* __restrict__ comm) {
    int row  = blockIdx.x >> 1;
    int half = blockIdx.x & 1;
    int col  = half * (HO / 2) + threadIdx.x * 4;
    int m    = mid[row];

    size_t off = (size_t)row * HO + col;
    float4 p0 = *(const float4*)(g_cpart + off);
    float4 p1 = *(const float4*)(g_cpart + 1ull * BB * HO + off);
    float4 p2 = *(const float4*)(g_cpart + 2ull * BB * HO + off);
    float4 p3 = *(const float4*)(g_cpart + 3ull * BB * HO + off);
    float4 bv = *(const float4*)(bo + m * HO + col);
    float4 o;
    o.x = (p0.x + p1.x + p2.x + p3.x + bv.x) * (1.0f / 7.0f);
    o.y = (p0.y + p1.y + p2.y + p3.y + bv.y) * (1.0f / 7.0f);
    o.z = (p0.z + p1.z + p2.z + p3.z + bv.z) * (1.0f / 7.0f);
    o.w = (p0.w + p1.w + p2.w + p3.w + bv.w) * (1.0f / 7.0f);
    *(float4*)(comm + off) = o;
}

extern "C" void kernel_launch(void* const* d_in, const int* in_sizes, int n_in,
                              void* d_out, int out_size) {
    const float* comm_in  = (const float*)d_in[0];
    const int*   inp      = (const int*)d_in[1];
    const float* prev_hid = (const float*)d_in[2];
    const int*   mid      = (const int*)d_in[4];
    const float* Wc       = (const float*)d_in[5];
    const float* bc       = (const float*)d_in[6];
    const float* Wr       = (const float*)d_in[7];
    const float* br       = (const float*)d_in[8];
    const float* Wa       = (const float*)d_in[9];
    const float* ba       = (const float*)d_in[10];
    const float* Wb       = (const float*)d_in[11];
    const float* bb       = (const float*)d_in[12];
    const float* Wo       = (const float*)d_in[13];
    const float* bo       = (const float*)d_in[14];
    const float* lut      = (const float*)d_in[15];
    const float* enc_bias = (const float*)d_in[16];

    float* out  = (float*)d_out;
    float* act  = out + ACT_OFF;
    float* base = out + BASE_OFF;
    float* hid  = out + HID_OFF;
    float* comm = out + COMM_OFF;

    k_zero<<<1, 32>>>();
    k_prep<<<BB, HH>>>(comm_in, mid);
    k_hidmm<<<dim3(MM, 4, 4), 128>>>(prev_hid, Wc, Wr);
    k_hidact<<<BB, 256>>>(mid, bc, br, lut, inp, enc_bias,
                          Wa, ba, Wb, bb, hid, act, base);
    k_commout<<<dim3(MM, 4, 4), 256>>>(hid, Wo);
    k_commep<<<2 * BB, 256>>>(mid, bo, comm);
}

// round 14
// speedup vs baseline: 1.2760x; 1.0220x over previous
#include <cuda_runtime.h>
#include <math.h>

#define BB   512
#define MM   32
#define NAG  8
#define HH   256
#define KQ   64           // K quarter
#define NACT 16
#define HO   (HH * NAG)   // 2048

#define ACT_OFF  0
#define BASE_OFF 8192
#define HID_OFF  8704
#define COMM_OFF 139776

__device__ float g_csum[BB * HH];
__device__ float g_part[4 * BB * HH];    // hid partials: one per kq (mats fused)
__device__ float g_cpart[4 * BB * HO];   // comm partials per kq
__device__ int   g_cnt[MM];              // zero at load; re-zeroed by k_commep
__device__ int   g_list[MM * BB];

// Per-example agent-sum + model-id grouping lists
__global__ void k_prep(const float* __restrict__ comm_in,
                       const int* __restrict__ mid) {
    int b = blockIdx.x;
    int h = threadIdx.x;
    const float* p = comm_in + b * NAG * HH + h;
    float s = 0.f;
#pragma unroll
    for (int a = 0; a < NAG; a++) s += p[a * HH];
    g_csum[b * HH + h] = s;
    if (h == 0) {
        int m = mid[b];
        int slot = atomicAdd(&g_cnt[m], 1);
        g_list[m * BB + slot] = b;
    }
}

// hid partial GEMM, BOTH matrices fused: acc = csum@Wc + prev@Wr for one kq slice.
// grid (32, 2 coltiles, 4 kq). 128 thr, 1 col/thread, 16-row chunks.
// Weight slabs 32KB+32KB = 64KB -> L1-resident repeats. One partial slab per kq.
__global__ void __launch_bounds__(128) k_hidmm(
                      const float* __restrict__ prev_hid,
                      const float* __restrict__ Wc,
                      const float* __restrict__ Wr) {
    int m = blockIdx.x;
    int n = g_cnt[m];
    if (n == 0) return;
    int col = blockIdx.y * 128 + threadIdx.x;
    int kq  = blockIdx.z;

    const float* WcP = Wc + m * HH * HH + kq * KQ * HH + col;
    const float* WrP = Wr + m * HH * HH + kq * KQ * HH + col;
    const float* Xc  = g_csum + kq * KQ;
    const float* Xp  = prev_hid + kq * KQ;
    float* P = g_part + kq * (BB * HH);

    __shared__ float xc[16][KQ];      // 4KB
    __shared__ float xp[16][KQ];      // 4KB
    __shared__ int   rows[16];

    for (int base = 0; base < n; base += 16) {
        int R = n - base; if (R > 16) R = 16;
        // stage 16 rows x 64 k of both inputs: 16 float4/row each
        for (int f = threadIdx.x; f < 16 * (KQ / 4); f += 128) {
            int r  = f >> 4;
            int k4 = f & 15;
            int rr  = (r < R) ? r : 0;
            int row = g_list[m * BB + base + rr];
            *(float4*)&xc[r][k4 * 4] = *(const float4*)&Xc[row * HH + k4 * 4];
            *(float4*)&xp[r][k4 * 4] = *(const float4*)&Xp[row * HH + k4 * 4];
            if (k4 == 0) rows[r] = row;
        }
        __syncthreads();

        float acc[16];
#pragma unroll
        for (int r = 0; r < 16; r++) acc[r] = 0.f;

        for (int k = 0; k < KQ; k += 8) {
            float wc[8], wr[8];
#pragma unroll
            for (int u = 0; u < 8; u++) {
                wc[u] = WcP[(k + u) * HH];
                wr[u] = WrP[(k + u) * HH];
            }
#pragma unroll
            for (int r = 0; r < 16; r++) {
#pragma unroll
                for (int u = 0; u < 8; u += 2) {
                    float2 c2 = *(const float2*)&xc[r][k + u];
                    float2 p2 = *(const float2*)&xp[r][k + u];
                    acc[r] = fmaf(c2.x, wc[u],     acc[r]);
                    acc[r] = fmaf(c2.y, wc[u + 1], acc[r]);
                    acc[r] = fmaf(p2.x, wr[u],     acc[r]);
                    acc[r] = fmaf(p2.y, wr[u + 1], acc[r]);
                }
            }
        }

        for (int r = 0; r < R; r++) P[rows[r] * HH + col] = acc[r];
        __syncthreads();
    }
}

// Fused: hid = tanh(sum of 4 partials + biases + lut); action softmax + baseline.
__global__ void __launch_bounds__(256) k_hidact(
                      const int* __restrict__ mid,
                      const float* __restrict__ bc, const float* __restrict__ br,
                      const float* __restrict__ lut, const int* __restrict__ inp,
                      const float* __restrict__ enc_bias,
                      const float* __restrict__ Wa, const float* __restrict__ ba,
                      const float* __restrict__ Wb, const float* __restrict__ bb,
                      float* __restrict__ hid,
                      float* __restrict__ act, float* __restrict__ base_out) {
    int b = blockIdx.x;
    int t = threadIdx.x;
    int m = mid[b];

    __shared__ float hsh[HH];
    __shared__ float sps[32 * 16];
    __shared__ float sb[8];

    {
        int c = t;   // 256 threads, 256 cols
        float v = bc[m * HH + c] + br[m * HH + c]
                + enc_bias[c] + lut[inp[b] * HH + c];
#pragma unroll
        for (int s = 0; s < 4; s++) v += g_part[s * (BB * HH) + b * HH + c];
        float h = tanhf(v);
        hid[b * HH + c] = h;
        hsh[c] = h;
    }
    __syncthreads();

    if (t < 128) {
        // action partials: aq = t&3 (4 actions each), kc = t>>2 (8 k's each)
        int aq = t & 3;
        int kc = t >> 2;
        const float4* WaP = (const float4*)(Wa + m * HH * NACT + aq * 4);
        float4 a4 = make_float4(0.f, 0.f, 0.f, 0.f);
#pragma unroll
        for (int j = 0; j < 8; j++) {
            int k = kc * 8 + j;
            float4 w = WaP[k * 4];
            float x = hsh[k];
            a4.x += x * w.x; a4.y += x * w.y; a4.z += x * w.z; a4.w += x * w.w;
        }
        *(float4*)&sps[kc * 16 + aq * 4] = a4;
    }
    {
        const float* WbP = Wb + m * HH;
        float pv = hsh[t] * WbP[t];
#pragma unroll
        for (int o = 16; o > 0; o >>= 1) pv += __shfl_xor_sync(0xffffffffu, pv, o);
        if ((t & 31) == 0) sb[t >> 5] = pv;
    }
    __syncthreads();

    if (t < NACT) {
        float v = ba[m * NACT + t];
#pragma unroll
        for (int kc = 0; kc < 32; kc++) v += sps[kc * 16 + t];
        float mx = v;
#pragma unroll
        for (int o = 8; o > 0; o >>= 1) mx = fmaxf(mx, __shfl_xor_sync(0xffffu, mx, o, 16));
        float ev = expf(v - mx);
        float sum = ev;
#pragma unroll
        for (int o = 8; o > 0; o >>= 1) sum += __shfl_xor_sync(0xffffu, sum, o, 16);
        act[b * NACT + t] = ev / sum;
    }
    if (t == 0) {
        float s = 0.f;
#pragma unroll
        for (int i = 0; i < 8; i++) s += sb[i];
        base_out[b] = s + bb[m];
    }
}

// comm partial GEMM. grid (32, 4 col-tiles of 512, 4 kq). 256 thr, float2/thread,
// 16-row chunks, float2 smem reads. Slab 128KB (L1-fit), 4096 warps.
__global__ void __launch_bounds__(256) k_commout(
                          const float* __restrict__ hid,
                          const float* __restrict__ Wo) {
    int m = blockIdx.x;
    int n = g_cnt[m];
    if (n == 0) return;
    int col0 = blockIdx.y * 512 + threadIdx.x * 2;
    int kq   = blockIdx.z;

    __shared__ float hs[16][KQ];      // 4KB
    __shared__ int   rows[16];

    const float2* WoP = (const float2*)(Wo + (size_t)m * HH * HO + (size_t)kq * KQ * HO + col0);
    float* P = g_cpart + (size_t)kq * BB * HO;

    for (int base = 0; base < n; base += 16) {
        int R = n - base; if (R > 16) R = 16;
        // stage 16 rows x 64 k of this kq slice: 16 float4/row, 1 per thread
        for (int f = threadIdx.x; f < 16 * (KQ / 4); f += 256) {
            int r  = f >> 4;
            int k4 = f & 15;
            int rr  = (r < R) ? r : 0;
            int row = g_list[m * BB + base + rr];
            *(float4*)&hs[r][k4 * 4] = *(const float4*)&hid[row * HH + kq * KQ + k4 * 4];
            if (k4 == 0) rows[r] = row;
        }
        __syncthreads();

        float2 acc[16];
#pragma unroll
        for (int r = 0; r < 16; r++) { acc[r].x = 0.f; acc[r].y = 0.f; }

        for (int k = 0; k < KQ; k += 8) {
            float2 w[8];
#pragma unroll
            for (int u = 0; u < 8; u++) w[u] = WoP[(k + u) * (HO / 2)];
#pragma unroll
            for (int r = 0; r < 16; r++) {
#pragma unroll
                for (int u = 0; u < 8; u += 2) {
                    float2 x2 = *(const float2*)&hs[r][k + u];
                    acc[r].x = fmaf(x2.x, w[u].x,     acc[r].x);
                    acc[r].y = fmaf(x2.x, w[u].y,     acc[r].y);
                    acc[r].x = fmaf(x2.y, w[u + 1].x, acc[r].x);
                    acc[r].y = fmaf(x2.y, w[u + 1].y, acc[r].y);
                }
            }
        }

        for (int r = 0; r < R; r++) {
            int row = rows[r];
            *(float2*)(P + (size_t)row * HO + col0) = acc[r];
        }
        __syncthreads();
    }
}

// comm epilogue: comm = (p0+p1+p2+p3 + bo[m]) / 7. grid (1024, 256), float4/thread.
// Also re-zeroes g_cnt for the next replay (device globals start zeroed at load,
// and every kernel_launch invocation leaves them zeroed -> deterministic).
__global__ void __launch_bounds__(256) k_commep(
                        const int* __restrict__ mid,
                        const float* __restrict__ bo,
                        float* __restrict__ comm) {
    int row  = blockIdx.x >> 1;
    int half = blockIdx.x & 1;
    int col  = half * (HO / 2) + threadIdx.x * 4;
    int m    = mid[row];

    size_t off = (size_t)row * HO + col;
    float4 p0 = *(const float4*)(g_cpart + off);
    float4 p1 = *(const float4*)(g_cpart + 1ull * BB * HO + off);
    float4 p2 = *(const float4*)(g_cpart + 2ull * BB * HO + off);
    float4 p3 = *(const float4*)(g_cpart + 3ull * BB * HO + off);
    float4 bv = *(const float4*)(bo + m * HO + col);
    float4 o;
    o.x = (p0.x + p1.x + p2.x + p3.x + bv.x) * (1.0f / 7.0f);
    o.y = (p0.y + p1.y + p2.y + p3.y + bv.y) * (1.0f / 7.0f);
    o.z = (p0.z + p1.z + p2.z + p3.z + bv.z) * (1.0f / 7.0f);
    o.w = (p0.w + p1.w + p2.w + p3.w + bv.w) * (1.0f / 7.0f);
    *(float4*)(comm + off) = o;

    if (blockIdx.x == 0 && threadIdx.x < MM) g_cnt[threadIdx.x] = 0;
}

extern "C" void kernel_launch(void* const* d_in, const int* in_sizes, int n_in,
                              void* d_out, int out_size) {
    const float* comm_in  = (const float*)d_in[0];
    const int*   inp      = (const int*)d_in[1];
    const float* prev_hid = (const float*)d_in[2];
    const int*   mid      = (const int*)d_in[4];
    const float* Wc       = (const float*)d_in[5];
    const float* bc       = (const float*)d_in[6];
    const float* Wr       = (const float*)d_in[7];
    const float* br       = (const float*)d_in[8];
    const float* Wa       = (const float*)d_in[9];
    const float* ba       = (const float*)d_in[10];
    const float* Wb       = (const float*)d_in[11];
    const float* bb       = (const float*)d_in[12];
    const float* Wo       = (const float*)d_in[13];
    const float* bo       = (const float*)d_in[14];
    const float* lut      = (const float*)d_in[15];
    const float* enc_bias = (const float*)d_in[16];

    float* out  = (float*)d_out;
    float* act  = out + ACT_OFF;
    float* base = out + BASE_OFF;
    float* hid  = out + HID_OFF;
    float* comm = out + COMM_OFF;

    k_prep<<<BB, HH>>>(comm_in, mid);
    k_hidmm<<<dim3(MM, 2, 4), 128>>>(prev_hid, Wc, Wr);
    k_hidact<<<BB, 256>>>(mid, bc, br, lut, inp, enc_bias,
                          Wa, ba, Wb, bb, hid, act, base);
    k_commout<<<dim3(MM, 4, 4), 256>>>(hid, Wo);
    k_commep<<<2 * BB, 256>>>(mid, bo, comm);
}